// round 12
// baseline (speedup 1.0000x reference)
#include <cuda_runtime.h>

// Row-normalize: out[b,i,j] = adj[b,i,j] / sum_j adj[b,i,j]  (nan/inf inv -> 0)
// Two tensors of [16, 1024, 1024] fp32; output = concat(out0, out1).
//
// Best shape (R2): 2 rows/CTA, 128 threads/row, 2 float4/thread, one barrier.
// NEW: __stwt write-through stores. Steady-state graph replay leaves ~60MB of
// dirty lines in L2 at kernel end, which drain between replays and serialize
// with the next replay's reads. Write-through pushes those writebacks into
// the kernel's 26% idle DRAM cycles, so each replay starts with a clean L2.

constexpr int N             = 1024;
constexpr int THREADS       = 256;
constexpr int ROWS_PER_CTA  = 2;
constexpr int TPR           = THREADS / ROWS_PER_CTA;   // 128
constexpr int WARPS_PER_ROW = TPR / 32;                 // 4

__global__ __launch_bounds__(THREADS, 8)
void row_norm_kernel(const float* __restrict__ in0,
                     const float* __restrict__ in1,
                     float* __restrict__ out,
                     int rows_per_tensor)   // 16384
{
    const int tid    = threadIdx.x;
    const int rgroup = tid >> 7;            // which row in this CTA
    const int t      = tid & (TPR - 1);     // lane within the row group

    const long long row = (long long)blockIdx.x * ROWS_PER_CTA + rgroup;
    const bool second = row >= rows_per_tensor;
    const float* __restrict__ src = second ? in1 : in0;
    const long long local_row = second ? (row - rows_per_tensor) : row;

    const float4* __restrict__ src_row =
        reinterpret_cast<const float4*>(src) + local_row * (N / 4);
    float4* __restrict__ dst_row =
        reinterpret_cast<float4*>(out) + row * (N / 4);

    // Two independent 128B loads in flight per thread.
    float4 v0 = __ldcs(src_row + t);
    float4 v1 = __ldcs(src_row + t + TPR);

    float partial = ((v0.x + v0.y) + (v0.z + v0.w))
                  + ((v1.x + v1.y) + (v1.z + v1.w));

    #pragma unroll
    for (int off = 16; off > 0; off >>= 1)
        partial += __shfl_xor_sync(0xFFFFFFFFu, partial, off);

    __shared__ float warp_sums[THREADS / 32];   // warps 0-3 row0, 4-7 row1
    const int wid = tid >> 5;
    if ((tid & 31) == 0) warp_sums[wid] = partial;
    __syncthreads();

    const float* ws = &warp_sums[rgroup * WARPS_PER_ROW];
    float deg = (ws[0] + ws[1]) + (ws[2] + ws[3]);
    float inv = 1.0f / deg;
    if (!isfinite(inv)) inv = 0.0f;

    v0.x *= inv; v0.y *= inv; v0.z *= inv; v0.w *= inv;
    v1.x *= inv; v1.y *= inv; v1.z *= inv; v1.w *= inv;
    __stwt(dst_row + t,       v0);   // write-through: no dirty L2 residue
    __stwt(dst_row + t + TPR, v1);
}

extern "C" void kernel_launch(void* const* d_in, const int* in_sizes, int n_in,
                              void* d_out, int out_size)
{
    const float* adj0 = (const float*)d_in[0];
    const float* adj1 = (const float*)d_in[1];
    float* out = (float*)d_out;

    const int rows_per_tensor = in_sizes[0] / N;          // 16384
    const int total_rows = 2 * rows_per_tensor;           // 32768
    const int grid = total_rows / ROWS_PER_CTA;           // 16384

    row_norm_kernel<<<grid, THREADS>>>(adj0, adj1, out, rows_per_tensor);
}

// round 13
// speedup vs baseline: 1.0300x; 1.0300x over previous
#include <cuda_runtime.h>

// Row-normalize: out[b,i,j] = adj[b,i,j] / sum_j adj[b,i,j]  (nan/inf inv -> 0)
// Two tensors of [16, 1024, 1024] fp32; output = concat(out0, out1).
//
// FINAL (R2 shape, best measured: 44.16us wall, 5.9 TB/s DRAM ~ roofline).
// 2 rows per CTA, 128 threads/row, 2 float4 per thread (MLP=2).
// Single __syncthreads per CTA; every thread re-sums the 4 warp partials
// itself (no broadcast barrier). Streaming cache hints (no reuse).
//
// Roofline evidence: 6 structurally distinct variants (occ 30-88%, MLP 2-16,
// burst vs pipelined, ldcg/ldcs x stcs/stwt) all pin at 5.7-5.9 TB/s in-kernel
// and 44.2-45.1us wall. Traffic (268 MB/launch) is irreducible; 268MB/44.2us
// = 6.07 TB/s = measured B300 mixed-R/W LTS ceiling.

constexpr int N            = 1024;                 // row length
constexpr int THREADS      = 256;
constexpr int ROWS_PER_CTA = 2;
constexpr int TPR          = THREADS / ROWS_PER_CTA;  // 128 threads per row
constexpr int WARPS_PER_ROW = TPR / 32;               // 4

__global__ __launch_bounds__(THREADS, 8)
void row_norm_kernel(const float* __restrict__ in0,
                     const float* __restrict__ in1,
                     float* __restrict__ out,
                     int rows_per_tensor)   // 16384
{
    const int tid    = threadIdx.x;
    const int rgroup = tid >> 7;            // 0 or 1: which row in this CTA
    const int t      = tid & (TPR - 1);     // lane within the row group

    const long long row = (long long)blockIdx.x * ROWS_PER_CTA + rgroup;
    const bool second = row >= rows_per_tensor;
    const float* __restrict__ src = second ? in1 : in0;
    const long long local_row = second ? (row - rows_per_tensor) : row;

    const float4* __restrict__ src_row =
        reinterpret_cast<const float4*>(src) + local_row * (N / 4);
    float4* __restrict__ dst_row =
        reinterpret_cast<float4*>(out) + row * (N / 4);

    // Two independent 128B loads in flight per thread.
    float4 v0 = __ldcs(src_row + t);
    float4 v1 = __ldcs(src_row + t + TPR);

    float partial = ((v0.x + v0.y) + (v0.z + v0.w))
                  + ((v1.x + v1.y) + (v1.z + v1.w));

    // Warp reduction (each warp is entirely within one row group)
    #pragma unroll
    for (int off = 16; off > 0; off >>= 1)
        partial += __shfl_xor_sync(0xFFFFFFFFu, partial, off);

    __shared__ float warp_sums[THREADS / 32];   // 8: warps 0-3 row0, 4-7 row1
    const int wid = tid >> 5;
    if ((tid & 31) == 0) warp_sums[wid] = partial;
    __syncthreads();

    // Every thread sums its row's 4 warp partials — no broadcast barrier.
    const float* ws = &warp_sums[rgroup * WARPS_PER_ROW];
    float deg = (ws[0] + ws[1]) + (ws[2] + ws[3]);
    float inv = 1.0f / deg;
    if (!isfinite(inv)) inv = 0.0f;

    v0.x *= inv; v0.y *= inv; v0.z *= inv; v0.w *= inv;
    v1.x *= inv; v1.y *= inv; v1.z *= inv; v1.w *= inv;
    __stcs(dst_row + t,        v0);
    __stcs(dst_row + t + TPR,  v1);
}

extern "C" void kernel_launch(void* const* d_in, const int* in_sizes, int n_in,
                              void* d_out, int out_size)
{
    const float* adj0 = (const float*)d_in[0];
    const float* adj1 = (const float*)d_in[1];
    float* out = (float*)d_out;

    const int rows_per_tensor = in_sizes[0] / N;          // 16384
    const int total_rows = 2 * rows_per_tensor;           // 32768
    const int grid = total_rows / ROWS_PER_CTA;           // 16384

    row_norm_kernel<<<grid, THREADS>>>(adj0, adj1, out, rows_per_tensor);
}